// round 13
// baseline (speedup 1.0000x reference)
#include <cuda_runtime.h>

// ---------------------------------------------------------------------------
// Photonic Clements mesh, N=128. One warp per column; lane t owns rows
// 8t..8t+7 as v0..v7. Round-10/11 skeleton (shfl hoist, rotating slots,
// predicate-free corners, pointer-strided loads, L1 prefetch) with
// ROUND 13: D*M*D*M fused into ONE precomputed complex 2x2 (G) per pair per
// iteration: 16 fma-ops / pair in a single 4-deep chain instead of 24 in four
// stages. First block (D0,M,X) and tail (D253,M,D254) use the raw table.
// Output serialization identical to rounds 4-12 (mode on out_size).
// ---------------------------------------------------------------------------

#define NCOLS   128
#define NLAYERS 255
#define NITER   126
#define FULL    0xffffffffu

#define AM_  0.97467943448089633f    // sqrt(1-0.05)
#define PP_  0.71063352017759484f    // sqrt(0.5+0.005)
#define QQ_  0.70356236397351441f    // sqrt(0.5-0.005)
#define AMP_ (AM_*PP_)
#define AMQ_ (AM_*QQ_)
#define AX_  0.98994949366116653f    // sqrt(1-0.02)
#define XC_  (AX_*0.1f)                       // aX*sqrt(CT)
#define XS_  (AX_*0.99498743710661995f)       // aX*sqrt(1-CT), corner scalar

// raw phase table: layer k, lane t reads float4s [k*64+2t], [k*64+2t+1]
__device__ float4 g_phase4[NLAYERS * 64];
// fused table: iter j (0..125), pair p (0..127): 2 float4 at [j*256 + 2p].
// +1024 pad: trailing distance-2 reloads (iters 126,127) stay in-bounds.
__device__ float4 g_G[NITER * 256 + 1024];

__global__ void phase_kernel(const float* __restrict__ theta_even) {
    int i = blockIdx.x * blockDim.x + threadIdx.x;
    if (i < NLAYERS * NCOLS) {
        float s, c;
        __sincosf(theta_even[i], &s, &c);
        reinterpret_cast<float2*>(g_phase4)[i] = make_float2(c, s);
    }
    if (i < NITER * NCOLS) {
        int j = i >> 7, p = i & 127;
        float sa, ca, sb, cb;
        __sincosf(theta_even[(2 * j + 1) * NCOLS + p], &sa, &ca);  // pa
        __sincosf(theta_even[(2 * j + 2) * NCOLS + p], &sb, &cb);  // pb
        const float A2 = AMP_ * AMP_, B2 = AMQ_ * AMQ_, AB = AMP_ * AMQ_;
        // G = M * D(pb) * M * D(pa), with M = [[A, iB],[iB, A]]:
        //   g00 = pa*(A2*pb - B2);  g01 = i*AB*(pb+1)
        //   g10 = pa*g01;           g11 = A2 - B2*pb
        float ux = A2 * cb - B2, uy = A2 * sb;
        float g00x = ca * ux - sa * uy, g00y = ca * uy + sa * ux;
        float wx = cb + 1.f, wy = sb;
        float g01x = -AB * wy, g01y = AB * wx;
        float g10x = ca * g01x - sa * g01y, g10y = ca * g01y + sa * g01x;
        float g11x = A2 - B2 * cb, g11y = -B2 * sb;
        g_G[j * 256 + 2 * p]     = make_float4(g00x, g00y, g01x, g01y);
        g_G[j * 256 + 2 * p + 1] = make_float4(g10x, g10y, g11x, g11y);
    }
}

// v *= (c + i s)
#define CMUL(v, c_, s_) do { \
    float _nx = fmaf((v).x, (c_), -(v).y * (s_)); \
    float _ny = fmaf((v).x, (s_),  (v).y * (c_)); \
    (v).x = _nx; (v).y = _ny; } while (0)

// [a;b] <- [[A,iB],[iB,A]][a;b]
#define MIX(a, b, A, B) do { \
    float _ar = fmaf((A), (a).x, -(B) * (b).y); \
    float _ai = fmaf((A), (a).y,  (B) * (b).x); \
    float _br = fmaf((A), (b).x, -(B) * (a).y); \
    float _bi = fmaf((A), (b).y,  (B) * (a).x); \
    (a).x = _ar; (a).y = _ai; (b).x = _br; (b).y = _bi; } while (0)

// general complex 2x2: q0 = (g00.x,g00.y,g01.x,g01.y), q1 = (g10..,g11..)
#define GAPP(a, b, q0, q1) do { \
    float _ax = fmaf((q0).x, (a).x, fmaf(-(q0).y, (a).y, fmaf((q0).z, (b).x, -(q0).w * (b).y))); \
    float _ay = fmaf((q0).x, (a).y, fmaf( (q0).y, (a).x, fmaf((q0).z, (b).y,  (q0).w * (b).x))); \
    float _bx = fmaf((q1).x, (a).x, fmaf(-(q1).y, (a).y, fmaf((q1).z, (b).x, -(q1).w * (b).y))); \
    float _by = fmaf((q1).x, (a).y, fmaf( (q1).y, (a).x, fmaf((q1).z, (b).y,  (q1).w * (b).x))); \
    (a).x = _ax; (a).y = _ay; (b).x = _bx; (b).y = _by; } while (0)

#define PF1(p) asm volatile("prefetch.global.L1 [%0];" :: "l"(p))

// one fused iteration: G on all 4 pairs (boundary pairs first, shfls overlap
// the middle pairs), then CROSS with corners folded into cA/cB coeffs.
#define ITERG(S) do { \
    GAPP(v0, v1, (S)[0], (S)[1]); \
    GAPP(v6, v7, (S)[6], (S)[7]); \
    float _nb0x = __shfl_down_sync(FULL, v0.x, 1);   /* lane t+1's v0 = row 8t+8 */ \
    float _nb0y = __shfl_down_sync(FULL, v0.y, 1); \
    float _nb7x = __shfl_up_sync  (FULL, v7.x, 1);   /* lane t-1's v7 = row 8t-1 */ \
    float _nb7y = __shfl_up_sync  (FULL, v7.y, 1); \
    GAPP(v2, v3, (S)[2], (S)[3]); \
    GAPP(v4, v5, (S)[4], (S)[5]); \
    MIX(v1, v2, XC_, XS_); \
    MIX(v3, v4, XC_, XS_); \
    MIX(v5, v6, XC_, XS_); \
    float _n7x = fmaf(cA7, v7.x, -cB7 * _nb0y); \
    float _n7y = fmaf(cA7, v7.y,  cB7 * _nb0x); \
    float _n0x = fmaf(cA0, v0.x, -cB0 * _nb7y); \
    float _n0y = fmaf(cA0, v0.y,  cB0 * _nb7x); \
    v7.x = _n7x; v7.y = _n7y; \
    v0.x = _n0x; v0.y = _n0y; } while (0)

#define LD8(S, p) do { \
    (S)[0] = (p)[0]; (S)[1] = (p)[1]; (S)[2] = (p)[2]; (S)[3] = (p)[3]; \
    (S)[4] = (p)[4]; (S)[5] = (p)[5]; (S)[6] = (p)[6]; (S)[7] = (p)[7]; } while (0)

__global__ void __launch_bounds__(32, 1)
mesh_kernel(const float* __restrict__ theta_in,
            const float* __restrict__ theta_out,
            float* __restrict__ out,
            int mode)   // 1 = real-only (16384 floats), 2 = planar (32768 floats)
{
    const int c = blockIdx.x;    // column (input port)
    const int t = threadIdx.x;   // lane: rows 8t..8t+7

    // per-lane boundary coefficients (corners folded in)
    const float cA7 = (t < 31) ? XC_ : XS_;
    const float cB7 = (t < 31) ? XS_ : 0.f;
    const float cA0 = (t > 0)  ? XC_ : XS_;
    const float cB0 = (t > 0)  ? XS_ : 0.f;

    float2 v0 = {0.f, 0.f}, v1 = {0.f, 0.f}, v2 = {0.f, 0.f}, v3 = {0.f, 0.f};
    float2 v4 = {0.f, 0.f}, v5 = {0.f, 0.f}, v6 = {0.f, 0.f}, v7 = {0.f, 0.f};

    // --- input: rows 2c, 2c+1 of column c of MMI_IN @ diag(e^{i th_in}) ---
    {
        float s, co;
        sincosf(theta_in[c], &s, &co);
        float2 ain = make_float2( AMP_ * co, AMP_ * s);   //  aM*p * e^{i th}
        float2 bin = make_float2(-AMQ_ * s,  AMQ_ * co);  // i*aM*q * e^{i th}
        int slot = 2 * c - 8 * t;
        if      (slot == 0) { v0 = ain; v1 = bin; }
        else if (slot == 2) { v2 = ain; v3 = bin; }
        else if (slot == 4) { v4 = ain; v5 = bin; }
        else if (slot == 6) { v6 = ain; v7 = bin; }
    }

    const float4* rb = g_phase4 + 2 * t;   // raw table, lane view

    // --- first block: D0, M, X (raw phases, hoisted form) ---
    {
        float4 p01 = rb[0], p23 = rb[1];
        CMUL(v0, p01.x, p01.y);
        CMUL(v6, p23.z, p23.w);
        MIX(v0, v1, AMP_, AMQ_);
        MIX(v6, v7, AMP_, AMQ_);
        float nb0x = __shfl_down_sync(FULL, v0.x, 1);
        float nb0y = __shfl_down_sync(FULL, v0.y, 1);
        float nb7x = __shfl_up_sync  (FULL, v7.x, 1);
        float nb7y = __shfl_up_sync  (FULL, v7.y, 1);
        CMUL(v2, p01.z, p01.w);
        CMUL(v4, p23.x, p23.y);
        MIX(v2, v3, AMP_, AMQ_);
        MIX(v4, v5, AMP_, AMQ_);
        MIX(v1, v2, XC_, XS_);
        MIX(v3, v4, XC_, XS_);
        MIX(v5, v6, XC_, XS_);
        float n7x = fmaf(cA7, v7.x, -cB7 * nb0y);
        float n7y = fmaf(cA7, v7.y,  cB7 * nb0x);
        float n0x = fmaf(cA0, v0.x, -cB0 * nb7y);
        float n0y = fmaf(cA0, v0.y,  cB0 * nb7x);
        v7.x = n7x; v7.y = n7y;
        v0.x = n0x; v0.y = n0y;
    }

    // --- 126 fused G iterations (layers 1..252), 63 unroll-2 trips.
    // Lane t's data per iter: 8 consecutive float4 at g_G + j*256 + 8t
    // (128B aligned -> one L1 line, one PF). Ping-pong slots, distance-2.
    const float4* gb = g_G + 8 * t;
    float4 s0[8], s1[8];
    LD8(s0, gb);          // iter 0
    LD8(s1, gb + 256);    // iter 1
    const float4* p0 = gb + 512;   // iter 2
    const float4* p1 = gb + 768;   // iter 3
    PF1(p0); PF1(p1);

#pragma unroll 1
    for (int m = 0; m < 63; m++) {
        ITERG(s0);
        LD8(s0, p0);
        p0 += 512; PF1(p0);
        ITERG(s1);
        LD8(s1, p1);
        p1 += 512; PF1(p1);
    }

    // --- tail: D253, M, D254 (raw phases; one exposed L2 fetch, negligible) ---
    {
        float4 ta0 = rb[253 * 64], ta1 = rb[253 * 64 + 1];
        float4 tb0 = rb[254 * 64], tb1 = rb[254 * 64 + 1];
        CMUL(v0, ta0.x, ta0.y);
        CMUL(v2, ta0.z, ta0.w);
        CMUL(v4, ta1.x, ta1.y);
        CMUL(v6, ta1.z, ta1.w);
        MIX(v0, v1, AMP_, AMQ_);
        MIX(v2, v3, AMP_, AMQ_);
        MIX(v4, v5, AMP_, AMQ_);
        MIX(v6, v7, AMP_, AMQ_);
        CMUL(v0, tb0.x, tb0.y);
        CMUL(v2, tb0.z, tb0.w);
        CMUL(v4, tb1.x, tb1.y);
        CMUL(v6, tb1.z, tb1.w);
    }

    // --- output rows jj = 4t..4t+3: MMI_OUT pair reduce, then e^{i th_out} ---
#define OUTP(va, vb, jj) do { \
        float _ox = fmaf(AMP_, (va).x, -AMQ_ * (vb).y); \
        float _oy = fmaf(AMP_, (va).y,  AMQ_ * (vb).x); \
        float _so, _co; sincosf(theta_out[jj], &_so, &_co); \
        float _re = _ox * _co - _oy * _so; \
        float _im = _ox * _so + _oy * _co; \
        if (mode == 1) { out[(jj) * NCOLS + c] = _re; } \
        else { out[(jj) * NCOLS + c] = _re; \
               out[NCOLS * NCOLS + (jj) * NCOLS + c] = _im; } } while (0)

    OUTP(v0, v1, 4 * t);
    OUTP(v2, v3, 4 * t + 1);
    OUTP(v4, v5, 4 * t + 2);
    OUTP(v6, v7, 4 * t + 3);
#undef OUTP
}

extern "C" void kernel_launch(void* const* d_in, const int* in_sizes, int n_in,
                              void* d_out, int out_size) {
    // Inputs identified by SIZE (theta_even = unique 32640-elem array;
    // theta_in precedes theta_out).
    const float* th_ev  = nullptr;
    const float* small_[2] = {nullptr, nullptr};
    int ns = 0;
    for (int i = 0; i < n_in && i < 3; i++) {
        if (in_sizes[i] > 1000) th_ev = (const float*)d_in[i];
        else if (ns < 2)        small_[ns++] = (const float*)d_in[i];
    }
    const float* th_in  = small_[0];
    const float* th_out = small_[1];

    int mode = (out_size == NCOLS * NCOLS) ? 1 : 2;  // 16384 -> real-only, else planar

    phase_kernel<<<(NLAYERS * NCOLS + 255) / 256, 256>>>(th_ev);
    mesh_kernel<<<NCOLS, 32>>>(th_in, th_out, (float*)d_out, mode);
}

// round 15
// speedup vs baseline: 2.0378x; 2.0378x over previous
#include <cuda_runtime.h>

// ---------------------------------------------------------------------------
// Photonic mesh simulation, N=128. FINAL: the best-measured structure
// (round 5, 27.4us) verbatim -- one warp per column, lane t owns rows
// 8t..8t+7 in registers, scalar FFMA, float2 phase table, distance-2
// double-buffered prefetch -- plus the only strictly-cheaper change that
// survived testing: __sincosf in the phase kernel (fast MUFU path; measured
// rel_err impact 4.6e-5, 20x under the 1e-3 threshold).
// (Resubmission of round 14: the bench container failed before measuring.)
// ---------------------------------------------------------------------------

#define NCOLS   128
#define NLAYERS 255
#define FULL    0xffffffffu

#define AM_  0.97467943448089633f    // sqrt(1-0.05)
#define PP_  0.71063352017759484f    // sqrt(0.5+0.005)
#define QQ_  0.70356236397351441f    // sqrt(0.5-0.005)
#define AMP_ (AM_*PP_)
#define AMQ_ (AM_*QQ_)
#define AX_  0.98994949366116653f    // sqrt(1-0.02)
#define XC_  (AX_*0.1f)                       // aX*sqrt(CT)
#define XS_  (AX_*0.99498743710661995f)       // aX*sqrt(1-CT), corner scalar

// phase table: layer k, lane t reads float4s [k*64 + 2t] and [k*64 + 2t + 1]
// (= phases for theta_even ports 4t..4t+3, stored as (cos,sin) float2 pairs)
__device__ float4 g_phase4[NLAYERS * 64];

__global__ void phase_kernel(const float* __restrict__ theta_even) {
    int i = blockIdx.x * blockDim.x + threadIdx.x;
    if (i < NLAYERS * NCOLS) {
        float s, c;
        __sincosf(theta_even[i], &s, &c);   // fast path; inputs in [0, 2pi)
        reinterpret_cast<float2*>(g_phase4)[i] = make_float2(c, s);
    }
}

// v *= (c + i s)
#define CMUL(v, c_, s_) do { \
    float _nx = fmaf((v).x, (c_), -(v).y * (s_)); \
    float _ny = fmaf((v).x, (s_),  (v).y * (c_)); \
    (v).x = _nx; (v).y = _ny; } while (0)

// [a;b] <- [[A, iB],[iB, A]] [a;b]
#define MIX(a, b, A, B) do { \
    float _ar = fmaf((A), (a).x, -(B) * (b).y); \
    float _ai = fmaf((A), (a).y,  (B) * (b).x); \
    float _br = fmaf((A), (b).x, -(B) * (a).y); \
    float _bi = fmaf((A), (b).y,  (B) * (a).x); \
    (a).x = _ar; (a).y = _ai; (b).x = _br; (b).y = _bi; } while (0)

#define APPLY_D(p01, p23) do { \
    CMUL(v0, (p01).x, (p01).y); \
    CMUL(v2, (p01).z, (p01).w); \
    CMUL(v4, (p23).x, (p23).y); \
    CMUL(v6, (p23).z, (p23).w); } while (0)

#define APPLY_M() do { \
    MIX(v0, v1, AMP_, AMQ_); \
    MIX(v2, v3, AMP_, AMQ_); \
    MIX(v4, v5, AMP_, AMQ_); \
    MIX(v6, v7, AMP_, AMQ_); } while (0)

#define APPLY_X() do { \
    float _nb0x = __shfl_down_sync(FULL, v0.x, 1); /* lane t+1's v0 = row 8t+8 */ \
    float _nb0y = __shfl_down_sync(FULL, v0.y, 1); \
    float _nb7x = __shfl_up_sync  (FULL, v7.x, 1); /* lane t-1's v7 = row 8t-1 */ \
    float _nb7y = __shfl_up_sync  (FULL, v7.y, 1); \
    MIX(v1, v2, XC_, XS_); \
    MIX(v3, v4, XC_, XS_); \
    MIX(v5, v6, XC_, XS_); \
    float _n7x = fmaf(XC_, v7.x, -XS_ * _nb0y); \
    float _n7y = fmaf(XC_, v7.y,  XS_ * _nb0x); \
    float _n0x = fmaf(XC_, v0.x, -XS_ * _nb7y); \
    float _n0y = fmaf(XC_, v0.y,  XS_ * _nb7x); \
    v7.x = (t < 31) ? _n7x : XS_ * v7.x;   /* row 255 corner */ \
    v7.y = (t < 31) ? _n7y : XS_ * v7.y; \
    v0.x = (t > 0)  ? _n0x : XS_ * v0.x;   /* row 0 corner */ \
    v0.y = (t > 0)  ? _n0y : XS_ * v0.y; } while (0)

#define PH(k, h) g_phase4[(k) * 64 + 2 * t + (h)]

__global__ void __launch_bounds__(32, 1)
mesh_kernel(const float* __restrict__ theta_in,
            const float* __restrict__ theta_out,
            float* __restrict__ out,
            int mode)   // 1 = real-only (16384 floats), 2 = planar (32768 floats)
{
    const int c = blockIdx.x;    // column (input port)
    const int t = threadIdx.x;   // lane: rows 8t..8t+7

    float2 v0 = {0.f, 0.f}, v1 = {0.f, 0.f}, v2 = {0.f, 0.f}, v3 = {0.f, 0.f};
    float2 v4 = {0.f, 0.f}, v5 = {0.f, 0.f}, v6 = {0.f, 0.f}, v7 = {0.f, 0.f};

    // --- input: rows 2c, 2c+1 of column c of MMI_IN @ diag(e^{i th_in}) ---
    {
        float s, co;
        sincosf(theta_in[c], &s, &co);
        float2 ain = make_float2( AMP_ * co, AMP_ * s);   //  aM*p * e^{i th}
        float2 bin = make_float2(-AMQ_ * s,  AMQ_ * co);  // i*aM*q * e^{i th}
        int slot = 2 * c - 8 * t;   // even slot 0/2/4/6 if rows in this lane
        if      (slot == 0) { v0 = ain; v1 = bin; }
        else if (slot == 2) { v2 = ain; v3 = bin; }
        else if (slot == 4) { v4 = ain; v5 = bin; }
        else if (slot == 6) { v6 = ain; v7 = bin; }
    }

    // --- D0, M, X ---
    {
        float4 p01 = PH(0, 0), p23 = PH(0, 1);
        APPLY_D(p01, p23);
        APPLY_M();
        APPLY_X();
    }

    // Virtual iteration j (0..126) consumes layers 2j+1 (a) and 2j+2 (b).
    // j = 0..125: D,M,D,M,X.  j = 126: tail D253, M, D254.
    // Distance-2 double-buffered prefetch; unroll-2 keeps slots in registers.
    float4 s0a0 = PH(1, 0), s0a1 = PH(1, 1), s0b0 = PH(2, 0), s0b1 = PH(2, 1);
    float4 s1a0 = PH(3, 0), s1a1 = PH(3, 1), s1b0 = PH(4, 0), s1b1 = PH(4, 1);

#pragma unroll 1
    for (int j = 0; j < 126; j += 2) {
        {   // iteration j: uses slot 0, prefetches j+2 into slot 0
            int jn = (j + 2 <= 126) ? (j + 2) : 126;     // clamp (redundant load ok)
            float4 na0 = PH(2 * jn + 1, 0), na1 = PH(2 * jn + 1, 1);
            float4 nb0 = PH(2 * jn + 2, 0), nb1 = PH(2 * jn + 2, 1);
            APPLY_D(s0a0, s0a1);
            APPLY_M();
            APPLY_D(s0b0, s0b1);
            APPLY_M();
            APPLY_X();
            s0a0 = na0; s0a1 = na1; s0b0 = nb0; s0b1 = nb1;
        }
        {   // iteration j+1: uses slot 1, prefetches j+3 into slot 1
            int jn = (j + 3 <= 126) ? (j + 3) : 126;
            float4 na0 = PH(2 * jn + 1, 0), na1 = PH(2 * jn + 1, 1);
            float4 nb0 = PH(2 * jn + 2, 0), nb1 = PH(2 * jn + 2, 1);
            APPLY_D(s1a0, s1a1);
            APPLY_M();
            APPLY_D(s1b0, s1b1);
            APPLY_M();
            APPLY_X();
            s1a0 = na0; s1a1 = na1; s1b0 = nb0; s1b1 = nb1;
        }
    }

    // --- tail j=126: D253, M, D254 (slot 0 holds layers 253/254) ---
    APPLY_D(s0a0, s0a1);
    APPLY_M();
    CMUL(v0, s0b0.x, s0b0.y);
    CMUL(v2, s0b0.z, s0b0.w);
    CMUL(v4, s0b1.x, s0b1.y);
    CMUL(v6, s0b1.z, s0b1.w);

    // --- output rows jj = 4t..4t+3: MMI_OUT pair reduce, then e^{i th_out} ---
#define OUTP(va, vb, jj) do { \
        float _ox = fmaf(AMP_, (va).x, -AMQ_ * (vb).y); \
        float _oy = fmaf(AMP_, (va).y,  AMQ_ * (vb).x); \
        float _so, _co; sincosf(theta_out[jj], &_so, &_co); \
        float _re = _ox * _co - _oy * _so; \
        float _im = _ox * _so + _oy * _co; \
        if (mode == 1) { out[(jj) * NCOLS + c] = _re; } \
        else { out[(jj) * NCOLS + c] = _re; \
               out[NCOLS * NCOLS + (jj) * NCOLS + c] = _im; } } while (0)

    OUTP(v0, v1, 4 * t);
    OUTP(v2, v3, 4 * t + 1);
    OUTP(v4, v5, 4 * t + 2);
    OUTP(v6, v7, 4 * t + 3);
#undef OUTP
}

extern "C" void kernel_launch(void* const* d_in, const int* in_sizes, int n_in,
                              void* d_out, int out_size) {
    // Inputs identified by SIZE (theta_even = unique 32640-elem array;
    // theta_in precedes theta_out in both dict and alphabetical order).
    const float* th_ev  = nullptr;
    const float* small_[2] = {nullptr, nullptr};
    int ns = 0;
    for (int i = 0; i < n_in && i < 3; i++) {
        if (in_sizes[i] > 1000) th_ev = (const float*)d_in[i];
        else if (ns < 2)        small_[ns++] = (const float*)d_in[i];
    }
    const float* th_in  = small_[0];
    const float* th_out = small_[1];

    int mode = (out_size == NCOLS * NCOLS) ? 1 : 2;  // 16384 -> real-only, else planar

    phase_kernel<<<(NLAYERS * NCOLS + 255) / 256, 256>>>(th_ev);
    mesh_kernel<<<NCOLS, 32>>>(th_in, th_out, (float*)d_out, mode);
}